// round 4
// baseline (speedup 1.0000x reference)
#include <cuda_runtime.h>

// MultiLayerRNNModel: 2-layer tanh RNN, T=2048, B=4096, I=3, H=5
// out = concat(out[T,B,H], h_n[2,B,H])
//
// R4: two independent batch streams per thread (b and b+2048). The two
// recurrences interleave in one warp and hide each other's fixed latencies
// (FMA/MUFU/LDS/WARPSYNC) that a single stream leaves exposed at ~1 warp/SMSP.
// Weights are shared registers. h0/h1 communicated per group of 8 lanes via
// paired float2 smem broadcast (1 STS.64 + 3 LDS per stream), ONE warpsync
// per step for both streams, double-buffered on t&1. Layers software-
// pipelined: iteration t computes h0(t) and h1(t-1).

#define T_LEN   2048
#define B_SZ    4096
#define XSTRIDE (B_SZ * 3)
#define OSTRIDE (B_SZ * 5)

__device__ __forceinline__ float tanh_fast(float v) {
    float y;
    asm("tanh.approx.f32 %0, %1;" : "=f"(y) : "f"(v));
    return y;
}

__global__ __launch_bounds__(32)
void rnn2_kernel(const float* __restrict__ x,
                 const float* __restrict__ hx,
                 const float* __restrict__ w_ih0,
                 const float* __restrict__ w_hh0,
                 const float* __restrict__ b_ih0,
                 const float* __restrict__ b_hh0,
                 const float* __restrict__ w_ih1,
                 const float* __restrict__ w_hh1,
                 const float* __restrict__ b_ih1,
                 const float* __restrict__ b_hh1,
                 float* __restrict__ out)
{
    // 8 slots (4 groups x 2 streams), 20-float stride => LDS.128 bases land on
    // banks {0,20,8,28,16,4,24,12} across the warp: conflict-free.
    __shared__ __align__(16) float buf[2][8][20];

    const int j  = threadIdx.x & 7;          // hidden unit (active j<5)
    const int g  = threadIdx.x >> 3;         // group in warp: 0..3
    const int G  = blockIdx.x * 4 + g;       // 0..2047 (grid exact)
    const int bA = G;                        // stream A batch
    const int bB = G + 2048;                 // stream B batch
    const int sA = g * 2, sB = g * 2 + 1;    // smem slots
    const bool act = (j < 5);
    const int  jj  = (j < 5) ? j : 0;

    // shared per-lane weights (row jj)
    float wi0[3], wh0[5], wi1[5], wh1[5];
    #pragma unroll
    for (int k = 0; k < 3; k++) wi0[k] = w_ih0[jj * 3 + k];
    #pragma unroll
    for (int k = 0; k < 5; k++) {
        wh0[k] = w_hh0[jj * 5 + k];
        wi1[k] = w_ih1[jj * 5 + k];
        wh1[k] = w_hh1[jj * 5 + k];
    }
    const float bias0 = b_ih0[jj] + b_hh0[jj];
    const float bias1 = b_ih1[jj] + b_hh1[jj];

    // states: at loop head h0v = h0(t-1), h1v = h1(t-2)
    float h0vA[5], h1vA[5], h0vB[5], h1vB[5];
    #pragma unroll
    for (int k = 0; k < 5; k++) {
        h0vA[k] = hx[bA * 5 + k];
        h1vA[k] = hx[B_SZ * 5 + bA * 5 + k];
        h0vB[k] = hx[bB * 5 + k];
        h1vB[k] = hx[B_SZ * 5 + bB * 5 + k];
    }

    const float* xbA = x + bA * 3;
    const float* xbB = x + bB * 3;
    float* outpA = out + bA * 5 + j;
    float* outpB = out + bB * 5 + j;

    // x prefetch queues, slot p holds x[t] with t&7 == p
    float xqA0[8], xqA1[8], xqA2[8];
    float xqB0[8], xqB1[8], xqB2[8];
    #pragma unroll
    for (int p = 0; p < 8; p++) {
        const float* xpA = xbA + p * XSTRIDE;
        xqA0[p] = xpA[0]; xqA1[p] = xpA[1]; xqA2[p] = xpA[2];
        const float* xpB = xbB + p * XSTRIDE;
        xqB0[p] = xpB[0]; xqB1[p] = xpB[1]; xqB2[p] = xpB[2];
    }

    float h0jA = 0.f, h1jA = 0.f, h0jB = 0.f, h1jB = 0.f;

// Pre-activations for one stream S at step t (h0(t) pre s, h1(t-1) pre u).
#define PRE(S, XP, sreg, ureg) {                                              \
    const float x0 = xq##S##0[XP], x1 = xq##S##1[XP], x2 = xq##S##2[XP];      \
    const float pre = fmaf(wi0[2], x2, fmaf(wi0[1], x1, fmaf(wi0[0], x0, bias0))); \
    const float a0 = fmaf(wh0[0], h0v##S[0], pre);                            \
    const float a1 = fmaf(wh0[2], h0v##S[2], wh0[1] * h0v##S[1]);             \
    const float a2 = fmaf(wh0[4], h0v##S[4], wh0[3] * h0v##S[3]);             \
    sreg = (a0 + a1) + a2;                                                    \
    const float ua = fmaf(wi1[0], h0v##S[0], bias1);                          \
    const float ub = fmaf(wi1[2], h0v##S[2], wi1[1] * h0v##S[1]);             \
    const float uc = fmaf(wi1[4], h0v##S[4], wi1[3] * h0v##S[3]);             \
    const float va = fmaf(wh1[1], h1v##S[1], wh1[0] * h1v##S[0]);             \
    const float vb = fmaf(wh1[4], h1v##S[4], fmaf(wh1[3], h1v##S[3], wh1[2] * h1v##S[2])); \
    ureg = ((ua + ub) + uc) + (va + vb);                                      \
}

#define READBACK(S, slot, BP) {                                               \
    const float4 qa = *(const float4*)&buf[BP][slot][0];                      \
    const float4 qb = *(const float4*)&buf[BP][slot][4];                      \
    const float2 qc = *(const float2*)&buf[BP][slot][8];                      \
    h0v##S[0] = qa.x; h1v##S[0] = qa.y; h0v##S[1] = qa.z; h1v##S[1] = qa.w;   \
    h0v##S[2] = qb.x; h1v##S[2] = qb.y; h0v##S[3] = qb.z; h1v##S[3] = qb.w;   \
    h0v##S[4] = qc.x; h1v##S[4] = qc.y;                                       \
}

// One pipelined step for both streams. XP == t&7, BP == t&1 (literals).
#define STEP(t, XP, BP) {                                                     \
    float sA_, uA_, sB_, uB_;                                                 \
    PRE(A, XP, sA_, uA_);                                                     \
    PRE(B, XP, sB_, uB_);                                                     \
    if ((t) + 8 < T_LEN) {                                                    \
        const float* xpA = xbA + ((t) + 8) * XSTRIDE;                         \
        xqA0[XP] = xpA[0]; xqA1[XP] = xpA[1]; xqA2[XP] = xpA[2];              \
        const float* xpB = xbB + ((t) + 8) * XSTRIDE;                         \
        xqB0[XP] = xpB[0]; xqB1[XP] = xpB[1]; xqB2[XP] = xpB[2];              \
    }                                                                         \
    h0jA = tanh_fast(sA_); h1jA = tanh_fast(uA_);                             \
    h0jB = tanh_fast(sB_); h1jB = tanh_fast(uB_);                             \
    *(float2*)&buf[BP][sA][j * 2] = make_float2(h0jA, h1jA);                  \
    *(float2*)&buf[BP][sB][j * 2] = make_float2(h0jB, h1jB);                  \
    __syncwarp();                                                             \
    READBACK(A, sA, BP);                                                      \
    READBACK(B, sB, BP);                                                      \
    if (act) {                                                                \
        outpA[((t) - 1) * OSTRIDE] = h1jA;                                    \
        outpB[((t) - 1) * OSTRIDE] = h1jB;                                    \
    }                                                                         \
}

    // ---- prologue t = 0: layer 0 only; pair-store (h0(0), h1(-1)) ----
    {
        float sA_, sB_;
        {
            const float x0 = xqA0[0], x1 = xqA1[0], x2 = xqA2[0];
            const float pre = fmaf(wi0[2], x2, fmaf(wi0[1], x1, fmaf(wi0[0], x0, bias0)));
            const float a0 = fmaf(wh0[0], h0vA[0], pre);
            const float a1 = fmaf(wh0[2], h0vA[2], wh0[1] * h0vA[1]);
            const float a2 = fmaf(wh0[4], h0vA[4], wh0[3] * h0vA[3]);
            sA_ = (a0 + a1) + a2;
        }
        {
            const float x0 = xqB0[0], x1 = xqB1[0], x2 = xqB2[0];
            const float pre = fmaf(wi0[2], x2, fmaf(wi0[1], x1, fmaf(wi0[0], x0, bias0)));
            const float a0 = fmaf(wh0[0], h0vB[0], pre);
            const float a1 = fmaf(wh0[2], h0vB[2], wh0[1] * h0vB[1]);
            const float a2 = fmaf(wh0[4], h0vB[4], wh0[3] * h0vB[3]);
            sB_ = (a0 + a1) + a2;
        }
        {
            const float* xpA = xbA + 8 * XSTRIDE;
            xqA0[0] = xpA[0]; xqA1[0] = xpA[1]; xqA2[0] = xpA[2];
            const float* xpB = xbB + 8 * XSTRIDE;
            xqB0[0] = xpB[0]; xqB1[0] = xpB[1]; xqB2[0] = xpB[2];
        }
        h0jA = tanh_fast(sA_);
        h0jB = tanh_fast(sB_);
        // pair = (h0(0), h1(-1)); lane j's h1v[j] is valid for j<5,
        // lanes 5..7 write pad slots that are never read.
        *(float2*)&buf[0][sA][j * 2] = make_float2(h0jA, h1vA[jj]);
        *(float2*)&buf[0][sB][j * 2] = make_float2(h0jB, h1vB[jj]);
        __syncwarp();
        READBACK(A, sA, 0);
        READBACK(B, sB, 0);
    }

    // ---- main loop: t = 1 .. 2040 in blocks of 8 (t0 = 8m+1) ----
    for (int t0 = 1; t0 < 2041; t0 += 8) {
        STEP(t0 + 0, 1, 1);
        STEP(t0 + 1, 2, 0);
        STEP(t0 + 2, 3, 1);
        STEP(t0 + 3, 4, 0);
        STEP(t0 + 4, 5, 1);
        STEP(t0 + 5, 6, 0);
        STEP(t0 + 6, 7, 1);
        STEP(t0 + 7, 0, 0);
    }

    // ---- tail: t = 2041 .. 2047 ----
    STEP(2041, 1, 1);
    STEP(2042, 2, 0);
    STEP(2043, 3, 1);
    STEP(2044, 4, 0);
    STEP(2045, 5, 1);
    STEP(2046, 6, 0);
    STEP(2047, 7, 1);

    // ---- epilogue: h1(2047) from h0v=h0(2047), h1v=h1(2046) ----
    {
        const float ua = fmaf(wi1[0], h0vA[0], bias1);
        const float ub = fmaf(wi1[2], h0vA[2], wi1[1] * h0vA[1]);
        const float uc = fmaf(wi1[4], h0vA[4], wi1[3] * h0vA[3]);
        const float va = fmaf(wh1[1], h1vA[1], wh1[0] * h1vA[0]);
        const float vb = fmaf(wh1[4], h1vA[4], fmaf(wh1[3], h1vA[3], wh1[2] * h1vA[2]));
        h1jA = tanh_fast(((ua + ub) + uc) + (va + vb));
    }
    {
        const float ua = fmaf(wi1[0], h0vB[0], bias1);
        const float ub = fmaf(wi1[2], h0vB[2], wi1[1] * h0vB[1]);
        const float uc = fmaf(wi1[4], h0vB[4], wi1[3] * h0vB[3]);
        const float va = fmaf(wh1[1], h1vB[1], wh1[0] * h1vB[0]);
        const float vb = fmaf(wh1[4], h1vB[4], fmaf(wh1[3], h1vB[3], wh1[2] * h1vB[2]));
        h1jB = tanh_fast(((ua + ub) + uc) + (va + vb));
    }

    if (act) {
        outpA[(T_LEN - 1) * OSTRIDE]     = h1jA;   // out[2047]
        outpB[(T_LEN - 1) * OSTRIDE]     = h1jB;
        outpA[T_LEN * OSTRIDE]           = h0jA;   // h_n[0]
        outpB[T_LEN * OSTRIDE]           = h0jB;
        outpA[T_LEN * OSTRIDE + OSTRIDE] = h1jA;   // h_n[1]
        outpB[T_LEN * OSTRIDE + OSTRIDE] = h1jB;
    }
#undef STEP
#undef PRE
#undef READBACK
}

extern "C" void kernel_launch(void* const* d_in, const int* in_sizes, int n_in,
                              void* d_out, int out_size)
{
    const float* x     = (const float*)d_in[0];
    const float* hx    = (const float*)d_in[1];
    const float* w_ih0 = (const float*)d_in[2];
    const float* w_hh0 = (const float*)d_in[3];
    const float* b_ih0 = (const float*)d_in[4];
    const float* b_hh0 = (const float*)d_in[5];
    const float* w_ih1 = (const float*)d_in[6];
    const float* w_hh1 = (const float*)d_in[7];
    const float* b_ih1 = (const float*)d_in[8];
    const float* b_hh1 = (const float*)d_in[9];
    float* out = (float*)d_out;

    // 512 blocks x 32 threads: 4 groups/block x 2 streams = 8 batches/block.
    // 512 * 8 = 4096 batches exactly; ~3.5 single-warp blocks per SM.
    rnn2_kernel<<<512, 32>>>(x, hx, w_ih0, w_hh0, b_ih0, b_hh0,
                             w_ih1, w_hh1, b_ih1, b_hh1, out);
}